// round 8
// baseline (speedup 1.0000x reference)
#include <cuda_runtime.h>
#include <cuda_bf16.h>
#include <cstdint>
#include <math.h>

// ---------------------------------------------------------------------------
// RoiProposal as ONE persistent kernel with software grid barriers.
// ---------------------------------------------------------------------------

#define NPROP 36864      // 64*64*9 anchors
#define KTOP  6000       // PRE_NMS_TOPN
#define KPAD  6016       // KTOP padded to multiple of 32
#define WORDS 188        // KPAD/32
#define TILES 188
#define NOUT  300
#define NBIN  16384      // fine histogram bins (key >> 18)
#define NCOARSE 256      // coarse histogram bins (key >> 24)
#define CAP   16384      // survivor capacity

// ------------------------------ scratch --------------------------------------
__device__ unsigned g_skey[NPROP];
__device__ int      g_hist[NBIN];
__device__ int      g_chist[NCOARSE];
__device__ unsigned long long g_k64[CAP];
__device__ int      g_iS[CAP];
__device__ int      g_rank[CAP];
__device__ int      g_cursor;
__device__ float g_px1[NPROP], g_py1[NPROP], g_px2[NPROP], g_py2[NPROP];
__device__ float g_tx1[KPAD], g_ty1[KPAD], g_tx2[KPAD], g_ty2[KPAD], g_ta[KPAD];
__device__ unsigned g_maskT[(size_t)WORDS * KPAD];   // [word][row]
__device__ unsigned g_bcount;   // barrier arrivals (returns to 0 each barrier)
__device__ unsigned g_bsense;   // barrier sense

__constant__ float c_AW[9] = {184.f, 368.f, 736.f, 128.f, 256.f, 512.f, 88.f, 176.f, 352.f};
__constant__ float c_AH[9] = {96.f, 192.f, 384.f, 128.f, 256.f, 512.f, 176.f, 352.f, 704.f};

// ------------------------------ grid barrier ---------------------------------
__device__ __forceinline__ void gsync(unsigned& sense) {
    __syncthreads();
    if (threadIdx.x == 0) {
        sense ^= 1u;
        __threadfence();
        unsigned old = atomicAdd(&g_bcount, 1u);
        if (old == gridDim.x - 1) {
            g_bcount = 0;
            __threadfence();
            atomicExch(&g_bsense, sense);
        } else {
            while (atomicAdd(&g_bsense, 0u) != sense) { }
        }
    }
    __syncthreads();
}

// ------------------------------ 256-thread inclusive scan --------------------
__device__ __forceinline__ int bscan256(int v, int t, int* ws) {
    #pragma unroll
    for (int d = 1; d < 32; d <<= 1) {
        int n = __shfl_up_sync(0xFFFFFFFFu, v, d);
        if ((t & 31) >= d) v += n;
    }
    if ((t & 31) == 31) ws[t >> 5] = v;
    __syncthreads();
    if (t < 32) {
        int w = (t < 8) ? ws[t] : 0;
        #pragma unroll
        for (int d = 1; d < 8; d <<= 1) {
            int n = __shfl_up_sync(0xFFFFFFFFu, w, d);
            if (t >= d) w += n;
        }
        if (t < 8) ws[t] = w;
    }
    __syncthreads();
    if (t >= 32) v += ws[(t >> 5) - 1];
    __syncthreads();     // protect ws for back-to-back calls
    return v;
}

// ------------------------------ NMS scan helpers -----------------------------
__device__ __forceinline__ void load_tile(unsigned (&dst)[32], int t, int T) {
    const uint4* q = reinterpret_cast<const uint4*>(
        &g_maskT[(size_t)t * KPAD + (size_t)T * 32]);
    #pragma unroll
    for (int i = 0; i < 8; i++) {
        uint4 v = q[i];
        dst[4*i+0] = v.x; dst[4*i+1] = v.y; dst[4*i+2] = v.z; dst[4*i+3] = v.w;
    }
}

__device__ __forceinline__ unsigned or_sel(const unsigned (&w)[32], unsigned km) {
    unsigned a0 = 0, a1 = 0, a2 = 0, a3 = 0;
    #pragma unroll
    for (int b = 0; b < 32; b += 4) {
        if (km & (1u << b))       a0 |= w[b];
        if (km & (1u << (b + 1))) a1 |= w[b + 1];
        if (km & (1u << (b + 2))) a2 |= w[b + 2];
        if (km & (1u << (b + 3))) a3 |= w[b + 3];
    }
    return (a0 | a1) | (a2 | a3);
}

__device__ __forceinline__ void diag_resolve(const unsigned (&D)[32], unsigned removed,
                                             unsigned& kept_out) {
    unsigned internal = removed, kept = 0u;
    #pragma unroll
    for (int b = 0; b < 32; b++) {
        if (!((internal >> b) & 1u)) { kept |= (1u << b); internal |= D[b]; }
    }
    kept_out = kept;
}

// =============================================================================
__global__ void __launch_bounds__(256, 1) mega_kernel(
    const float* __restrict__ cls, const float* __restrict__ bbox,
    float* __restrict__ out)
{
    const int t = threadIdx.x;
    const int blk = blockIdx.x;
    const int G = gridDim.x;
    const int gtid = blk * 256 + t;
    const int gstr = G * 256;
    unsigned sense = *((volatile unsigned*)&g_bsense);

    __shared__ int s_ws[8];
    __shared__ int s_cb, s_above, s_tb;
    __shared__ unsigned long long s_jk[512];
    __shared__ float sx1[32], sy1[32], sx2[32], sy2[32], sa[32];
    __shared__ unsigned s_keep[2];
    __shared__ int s_tot[2];
    __shared__ int s_sidx[NOUT];
    __shared__ int s_C;

    // ---- P0: zero scratch + pads ----
    for (int i = gtid; i < NBIN; i += gstr) g_hist[i] = 0;
    for (int i = gtid; i < NCOARSE; i += gstr) g_chist[i] = 0;
    for (int i = gtid; i < CAP; i += gstr) { g_rank[i] = 0; g_k64[i] = 0ull; }
    for (int i = KTOP + gtid; i < KPAD; i += gstr) {
        g_tx1[i] = -1e8f; g_ty1[i] = -1e8f; g_tx2[i] = -1e8f; g_ty2[i] = -1e8f;
        g_ta[i] = 1.f;
    }
    if (gtid == 0) g_cursor = 0;
    gsync(sense);

    // ---- P1: proposals + keys + two-level histogram ----
    for (int i = gtid; i < NPROP; i += gstr) {
        int a = i % 9;
        int cell = i / 9;
        float axc = (float)((cell % 64) * 16 + 8);
        float ayc = (float)((cell / 64) * 16 + 8);
        float aw = c_AW[a];
        float ah = c_AH[a];

        const float* cp = cls + cell * 18 + a * 2;
        float s0 = cp[0], s1 = cp[1];
        const float* dp = bbox + cell * 36 + a * 4;
        float dx = dp[0], dy = dp[1], dw = dp[2], dh = dp[3];

        // explicit .rn ops (no FMA contraction; match XLA)
        float pxc = __fadd_rn(__fmul_rn(dx, aw), axc);
        float pyc = __fadd_rn(__fmul_rn(dy, ah), ayc);
        float pw  = __fmul_rn(expf(dw), aw);
        float ph  = __fmul_rn(expf(dh), ah);
        float hx  = __fmul_rn(0.5f, pw);
        float hy  = __fmul_rn(0.5f, ph);
        float x1 = fminf(fmaxf(__fsub_rn(pxc, hx), 0.f), 1023.f);
        float x2 = fminf(fmaxf(__fadd_rn(pxc, hx), 0.f), 1023.f);
        float y1 = fminf(fmaxf(__fsub_rn(pyc, hy), 0.f), 1023.f);
        float y2 = fminf(fmaxf(__fadd_rn(pyc, hy), 0.f), 1023.f);

        bool valid = (__fadd_rn(__fsub_rn(x2, x1), 1.f) >= 16.f) &&
                     (__fadd_rn(__fsub_rn(y2, y1), 1.f) >= 16.f);

        float m  = fmaxf(s0, s1);
        float e0 = expf(__fsub_rn(s0, m));
        float e1 = expf(__fsub_rn(s1, m));
        float sc = __fdiv_rn(e1, __fadd_rn(e0, e1));
        if (!valid) sc = -INFINITY;

        g_px1[i] = x1; g_py1[i] = y1; g_px2[i] = x2; g_py2[i] = y2;

        unsigned ub = __float_as_uint(sc);
        ub = (ub & 0x80000000u) ? ~ub : (ub | 0x80000000u);
        g_skey[i] = ub;
        atomicAdd(&g_hist[ub >> 18], 1);
        atomicAdd(&g_chist[ub >> 24], 1);
    }
    gsync(sense);

    // ---- P2: threshold bin (redundant per block; coarse -> fine drill) ----
    {
        int cval = g_chist[255 - t];               // descending coarse bins
        int cincl = bscan256(cval, t, s_ws);
        if (cincl >= KTOP && (cincl - cval) < KTOP) { s_cb = 255 - t; s_above = cincl - cval; }
        __syncthreads();
        int cb = s_cb;
        int above = s_above;
        int fval = (t < 64) ? g_hist[cb * 64 + 63 - t] : 0;
        int fincl = bscan256(fval, t, s_ws);
        if (t < 64) {
            int tot = above + fincl;
            if (tot >= KTOP && (tot - fval) < KTOP) s_tb = cb * 64 + 63 - t;
        }
        __syncthreads();
    }
    unsigned tb = (unsigned)s_tb;

    // ---- P3: compaction (unordered; ranks are set-based on unique keys) ----
    for (int i = gtid; i < NPROP; i += gstr) {
        unsigned key = g_skey[i];
        if ((key >> 18) >= tb) {
            int pos = atomicAdd(&g_cursor, 1);
            if (pos < CAP) {
                g_k64[pos] = ((unsigned long long)key << 32) |
                             (unsigned long long)(0xFFFFFFFFu - (unsigned)i);
                g_iS[pos] = i;
            }
        }
    }
    gsync(sense);

    // ---- P4: exact pairwise ranking (512x512 tiles, grid-strided) ----
    int S = atomicAdd(&g_cursor, 0);
    if (S > CAP) S = CAP;
    {
        int nT = (S + 511) >> 9;
        int ntiles = nT * nT;
        for (int tau = blk; tau < ntiles; tau += G) {
            int ib = (tau / nT) << 9;
            int jb = (tau % nT) << 9;
            __syncthreads();
            s_jk[t]       = g_k64[jb + t];
            s_jk[t + 256] = g_k64[jb + t + 256];
            __syncthreads();
            int i1 = ib + t, i2 = ib + t + 256;
            unsigned long long k1 = g_k64[i1];
            unsigned long long k2 = g_k64[i2];
            int c1 = 0, c2 = 0;
            #pragma unroll 8
            for (int jj = 0; jj < 512; jj++) {
                unsigned long long kj = s_jk[jj];
                c1 += (kj > k1);
                c2 += (kj > k2);
            }
            if (i1 < S && c1) atomicAdd(&g_rank[i1], c1);
            if (i2 < S && c2) atomicAdd(&g_rank[i2], c2);
        }
    }
    gsync(sense);

    // ---- P5: scatter boxes to sorted slots ----
    for (int i = gtid; i < S; i += gstr) {
        int r = g_rank[i];
        if (r < KTOP) {
            int idx = g_iS[i];
            float x1 = g_px1[idx], y1 = g_py1[idx], x2 = g_px2[idx], y2 = g_py2[idx];
            g_tx1[r] = x1; g_ty1[r] = y1; g_tx2[r] = x2; g_ty2[r] = y2;
            g_ta[r] = __fmul_rn(__fadd_rn(__fsub_rn(x2, x1), 1.f),
                                __fadd_rn(__fsub_rn(y2, y1), 1.f));
        }
    }
    gsync(sense);

    // ---- P6: IoU suppression bitmask (upper triangle, grid-strided items) ----
    for (int m = blk; m < 24 * 188; m += G) {
        int rb = m / 188;
        int wx = m - rb * 188;
        if (wx < 8 * rb) continue;            // uniform per block
        __syncthreads();
        if (t < 32) {
            int c = wx * 32 + t;
            sx1[t] = g_tx1[c]; sy1[t] = g_ty1[c];
            sx2[t] = g_tx2[c]; sy2[t] = g_ty2[c];
            sa[t]  = g_ta[c];
        }
        __syncthreads();
        int r = rb * 256 + t;
        unsigned w = 0;
        if (r < KTOP) {
            float x1 = g_tx1[r], y1 = g_ty1[r], x2 = g_tx2[r], y2 = g_ty2[r], ar = g_ta[r];
            #pragma unroll
            for (int b = 0; b < 32; b++) {
                int c = wx * 32 + b;
                float ix1 = fmaxf(x1, sx1[b]);
                float iy1 = fmaxf(y1, sy1[b]);
                float ix2 = fminf(x2, sx2[b]);
                float iy2 = fminf(y2, sy2[b]);
                float iw = fmaxf(__fadd_rn(__fsub_rn(ix2, ix1), 1.f), 0.f);
                float ih = fmaxf(__fadd_rn(__fsub_rn(iy2, iy1), 1.f), 0.f);
                float inter = __fmul_rn(iw, ih);
                float uni = __fsub_rn(__fadd_rn(ar, sa[b]), inter);
                float iou = __fdiv_rn(inter, uni);
                bool bit = (c > r) && (c < KTOP) && (iou > 0.7f);
                w |= ((unsigned)bit) << b;
            }
        }
        if (r < KPAD) g_maskT[(size_t)wx * KPAD + r] = w;
    }
    gsync(sense);

    // ---- P7: sequential greedy NMS scan + output (block 0 only) ----
    if (blk != 0) return;

    bool act = (t < WORDS);
    unsigned D[32], Abuf[32], Bbuf[32];
    unsigned removed = 0;
    int stop = TILES - 1;

    if (act) load_tile(D, t, t);
    if (act && t >= 1) load_tile(Abuf, t, 0);

    #pragma unroll 1
    for (int T = 0; T < TILES; T += 2) {
        if (act && t >= T + 2 && T + 1 < TILES) load_tile(Bbuf, t, T + 1);
        if (t == T) {
            unsigned kept;
            diag_resolve(D, removed, kept);
            s_keep[0] = kept;
            unsigned cv = (T == TILES - 1) ? (kept & 0xFFFFu) : kept;
            s_tot[0] = ((T == 0) ? 0 : s_tot[1]) + __popc(cv);
        }
        __syncthreads();
        {
            unsigned km = s_keep[0];
            if (act && t >= T) {
                if (t == T) removed |= or_sel(D, km);
                else        removed |= or_sel(Abuf, km);
            }
            if (s_tot[0] >= NOUT) { stop = T; break; }
        }
        if (T + 1 < TILES) {
            if (act && t >= T + 3 && T + 2 < TILES) load_tile(Abuf, t, T + 2);
            if (t == T + 1) {
                unsigned kept;
                diag_resolve(D, removed, kept);
                s_keep[1] = kept;
                unsigned cv = (T + 1 == TILES - 1) ? (kept & 0xFFFFu) : kept;
                s_tot[1] = s_tot[0] + __popc(cv);
            }
            __syncthreads();
            unsigned km = s_keep[1];
            if (act && t >= T + 1) {
                if (t == T + 1) removed |= or_sel(D, km);
                else            removed |= or_sel(Bbuf, km);
            }
            if (s_tot[1] >= NOUT) { stop = T + 1; break; }
        }
    }
    __syncthreads();

    // ---- P8: select first 300 + write output (same block; removed in regs) ----
    int L = min(KTOP, 32 * (stop + 1));
    int nb = L - 32 * t;
    nb = nb < 0 ? 0 : (nb > 32 ? 32 : nb);
    unsigned vmask = (nb >= 32) ? 0xFFFFFFFFu : ((nb > 0) ? ((1u << nb) - 1u) : 0u);

    unsigned rem = act ? removed : 0u;
    unsigned kept = (~rem) & vmask;
    int cnt = __popc(kept);
    int incl = bscan256(cnt, t, s_ws);
    int excl = incl - cnt;
    if (t == 255) s_C = incl;
    __syncthreads();
    int C = s_C;

    if (excl < NOUT && kept) {
        int r = excl;
        #pragma unroll 4
        for (int b = 0; b < 32; b++) {
            if ((kept >> b) & 1u) {
                if (r < NOUT) s_sidx[r] = t * 32 + b;
                r++;
            }
        }
    }
    __syncthreads();

    if (C < NOUT) {   // fill with suppressed (index ascending)
        unsigned sup = rem & vmask;
        int cnt2 = __popc(sup);
        int incl2 = bscan256(cnt2, t, s_ws);
        int base = C + (incl2 - cnt2);
        if (base < NOUT && sup) {
            #pragma unroll 4
            for (int b = 0; b < 32; b++) {
                if ((sup >> b) & 1u) {
                    if (base < NOUT) s_sidx[base] = t * 32 + b;
                    base++;
                }
            }
        }
        __syncthreads();
    }

    for (int r = t; r < NOUT; r += 256) {
        int idx = s_sidx[r];
        out[5 * r + 0] = 0.f;
        out[5 * r + 1] = g_tx1[idx];
        out[5 * r + 2] = g_ty1[idx];
        out[5 * r + 3] = g_tx2[idx];
        out[5 * r + 4] = g_ty2[idx];
    }
}

// ------------------------------ launch ---------------------------------------
extern "C" void kernel_launch(void* const* d_in, const int* in_sizes, int n_in,
                              void* d_out, int out_size) {
    const float* cls  = (const float*)d_in[0];   // (1,64,64,18)
    const float* bbox = (const float*)d_in[1];   // (1,64,64,36)
    float* out = (float*)d_out;                  // (300,5)

    int dev = 0;
    cudaGetDevice(&dev);
    int sms = 0;
    cudaDeviceGetAttribute(&sms, cudaDevAttrMultiProcessorCount, dev);
    int maxb = 0;
    cudaOccupancyMaxActiveBlocksPerMultiprocessor(&maxb, mega_kernel, 256, 0);
    int G = (maxb >= 1 && sms >= 1) ? sms : 1;   // all blocks co-resident (wave 1)

    mega_kernel<<<G, 256>>>(cls, bbox, out);
}